// round 9
// baseline (speedup 1.0000x reference)
#include <cuda_runtime.h>
#include <cuda_bf16.h>

#define N_NODES 10000
#define NHID    128
#define NEDGE   320000
#define NT      79            // ceil(10000/128)
#define NPAD    (NT * 128)    // 10112
#define NB      (NT * (NT + 1) / 2)   // 3160 upper-tri blocks
#define GEMM_SMEM 65536       // A+B tiles only (no epilogue staging)

__device__ __forceinline__ unsigned smem_u32(const void* p) {
    unsigned a;
    asm("{ .reg .u64 t; cvta.to.shared.u64 t, %1; cvt.u32.u64 %0, t; }"
        : "=r"(a) : "l"(p));
    return a;
}

// ---------------- scratch ----------------
__device__ float          g_xw  [N_NODES * NHID];
__device__ __nv_bfloat16  g_hb  [NPAD   * NHID];   // pad rows stay 0 (zero-init, never written)
__device__ float          g_dinv[N_NODES];
__device__ int            g_cnt [N_NODES];
__device__ int            g_base[N_NODES];
__device__ int            g_cur [N_NODES];
__device__ int            g_src [NEDGE];

// ---- zero counters (graph replay: re-run every launch) ----
__global__ void k_zero() {
    int i = blockIdx.x * blockDim.x + threadIdx.x;
    if (i < N_NODES) { g_cnt[i] = 0; g_cur[i] = 0; }
}

// ---- histogram of incoming edges at target ----
__global__ void k_hist(const int* __restrict__ p) {
    int e = blockIdx.x * blockDim.x + threadIdx.x;
    if (e < NEDGE) {
        int c = p[NEDGE + e];
        if ((unsigned)c >= N_NODES) c = 0;
        atomicAdd(&g_cnt[c], 1);
    }
}

// ---- exclusive prefix sum (single block) ----
__global__ void k_scan() {
    __shared__ int sums[256];
    const int CH = 40;
    int t = threadIdx.x;
    int s = 0;
    for (int j = 0; j < CH; j++) {
        int n = t * CH + j;
        if (n < N_NODES) s += g_cnt[n];
    }
    sums[t] = s;
    __syncthreads();
    for (int off = 1; off < 256; off <<= 1) {
        int v = (t >= off) ? sums[t - off] : 0;
        __syncthreads();
        sums[t] += v;
        __syncthreads();
    }
    int run = (t > 0) ? sums[t - 1] : 0;
    for (int j = 0; j < CH; j++) {
        int n = t * CH + j;
        if (n < N_NODES) { g_base[n] = run; run += g_cnt[n]; }
    }
}

// ---- CSR fill + dinv fused ----
__global__ void k_fill(const int* __restrict__ p) {
    int e = blockIdx.x * blockDim.x + threadIdx.x;
    if (e < N_NODES) g_dinv[e] = rsqrtf((float)g_cnt[e] + 1.0f);
    if (e < NEDGE) {
        int r = p[e], c = p[NEDGE + e];
        if ((unsigned)r >= N_NODES) r = 0;
        if ((unsigned)c >= N_NODES) c = 0;
        int pos = g_base[c] + atomicAdd(&g_cur[c], 1);
        g_src[pos] = r;
    }
}

// ---- xw = x @ W ----
__global__ void k_xw(const float* __restrict__ x, const float* __restrict__ W) {
    __shared__ float xs[NHID];
    int n = blockIdx.x;
    int t = threadIdx.x;
    xs[t] = x[n * NHID + t];
    __syncthreads();
    float acc = 0.0f;
#pragma unroll 8
    for (int k = 0; k < NHID; k++)
        acc = fmaf(xs[k], W[k * NHID + t], acc);
    g_xw[n * NHID + t] = acc;
}

// ---- SpMM gather (smem-staged srcs, 2 accumulators) + self-loop + bias + relu ----
__global__ void __launch_bounds__(128) k_spmm(const float* __restrict__ b) {
    __shared__ int   ssrc[64];
    __shared__ float swt [64];
    int c = blockIdx.x;
    int t = threadIdx.x;
    int base = g_base[c];
    int cnt  = g_cnt[c];
    float acc0 = 0.0f, acc1 = 0.0f;
    for (int chunk = 0; chunk < cnt; chunk += 64) {
        int m = min(64, cnt - chunk);
        __syncthreads();
        if (t < m) {
            int s = g_src[base + chunk + t];
            ssrc[t] = s;
            swt [t] = g_dinv[s];
        }
        __syncthreads();
        int i = 0;
        for (; i + 1 < m; i += 2) {
            acc0 = fmaf(swt[i],     g_xw[ssrc[i]     * NHID + t], acc0);
            acc1 = fmaf(swt[i + 1], g_xw[ssrc[i + 1] * NHID + t], acc1);
        }
        if (i < m)
            acc0 = fmaf(swt[i], g_xw[ssrc[i] * NHID + t], acc0);
    }
    float dc = g_dinv[c];
    float v  = dc * (acc0 + acc1) + dc * dc * g_xw[c * NHID + t] + b[t];
    g_hb[c * NHID + t] = __float2bfloat16(fmaxf(v, 0.0f));
}

// ---- out = h @ h^T : bf16 mma.sync + ldmatrix; register-direct epilogue ----
__global__ void __launch_bounds__(256) k_gemm(float* __restrict__ out) {
    extern __shared__ char smem[];
    // map linear block -> (bi, bj), bi <= bj
    int tlin = blockIdx.x;
    int bi = (int)(NT + 0.5 - sqrt((NT + 0.5) * (NT + 0.5) - 2.0 * tlin));
    while (bi + 1 <= NT - 1 && (bi + 1) * NT - ((bi + 1) * bi) / 2 <= tlin) bi++;
    while (bi > 0 && bi * NT - (bi * (bi - 1)) / 2 > tlin) bi--;
    int bj = bi + (tlin - (bi * NT - (bi * (bi - 1)) / 2));
    bool diag = (bi == bj);

    unsigned sA = smem_u32(smem);
    unsigned sB = sA + 32768u;

    int t = threadIdx.x, lane = t & 31, wid = t >> 5;
    const __nv_bfloat16* gA = g_hb + (size_t)bi * 128 * NHID;
    const __nv_bfloat16* gB = g_hb + (size_t)bj * 128 * NHID;

    // load tiles (8 passes x 256 threads x 16B); XOR-16B swizzle per row
#pragma unroll
    for (int p = 0; p < 8; p++) {
        int chunk = p * 256 + t;
        int row = chunk >> 4, kc = chunk & 15;
        unsigned off = (unsigned)row * 256u + (unsigned)((kc ^ (row & 7)) << 4);
        *(uint4*)(smem + off) = *(const uint4*)(gA + row * NHID + kc * 8);
        if (!diag)
            *(uint4*)(smem + 32768 + off) = *(const uint4*)(gB + row * NHID + kc * 8);
    }
    __syncthreads();

    unsigned bB = diag ? sA : sB;
    int wm = wid & 3;
    int wn = wid >> 2;
    int mat = lane >> 3, rin = lane & 7;
    int rowoff = rin + (mat & 1) * 8;
    int khalf  = mat >> 1;

    float acc[2][8][4] = {};

#pragma unroll
    for (int ks = 0; ks < 8; ks++) {
        int kc = ks * 2 + khalf;
        unsigned a[2][4];
#pragma unroll
        for (int mi = 0; mi < 2; mi++) {
            int row = wm * 32 + mi * 16 + rowoff;
            unsigned addr = sA + (unsigned)row * 256u + (unsigned)((kc ^ (row & 7)) << 4);
            asm volatile("ldmatrix.sync.aligned.m8n8.x4.shared.b16 {%0,%1,%2,%3}, [%4];"
                : "=r"(a[mi][0]), "=r"(a[mi][1]), "=r"(a[mi][2]), "=r"(a[mi][3])
                : "r"(addr));
        }
        unsigned bf[4][4];
#pragma unroll
        for (int nb = 0; nb < 4; nb++) {
            int row = wn * 64 + nb * 16 + rowoff;
            unsigned addr = bB + (unsigned)row * 256u + (unsigned)((kc ^ (row & 7)) << 4);
            asm volatile("ldmatrix.sync.aligned.m8n8.x4.shared.b16 {%0,%1,%2,%3}, [%4];"
                : "=r"(bf[nb][0]), "=r"(bf[nb][1]), "=r"(bf[nb][2]), "=r"(bf[nb][3])
                : "r"(addr));
        }
#pragma unroll
        for (int mi = 0; mi < 2; mi++)
#pragma unroll
            for (int nb = 0; nb < 4; nb++) {
                float* d0 = acc[mi][nb * 2 + 0];
                float* d1 = acc[mi][nb * 2 + 1];
                asm volatile(
                    "mma.sync.aligned.m16n8k16.row.col.f32.bf16.bf16.f32 "
                    "{%0,%1,%2,%3}, {%4,%5,%6,%7}, {%8,%9}, {%0,%1,%2,%3};"
                    : "+f"(d0[0]), "+f"(d0[1]), "+f"(d0[2]), "+f"(d0[3])
                    : "r"(a[mi][0]), "r"(a[mi][1]), "r"(a[mi][2]), "r"(a[mi][3]),
                      "r"(bf[nb][0]), "r"(bf[nb][2]));
                asm volatile(
                    "mma.sync.aligned.m16n8k16.row.col.f32.bf16.bf16.f32 "
                    "{%0,%1,%2,%3}, {%4,%5,%6,%7}, {%8,%9}, {%0,%1,%2,%3};"
                    : "+f"(d1[0]), "+f"(d1[1]), "+f"(d1[2]), "+f"(d1[3])
                    : "r"(a[mi][0]), "r"(a[mi][1]), "r"(a[mi][2]), "r"(a[mi][3]),
                      "r"(bf[nb][1]), "r"(bf[nb][3]));
            }
    }

    // register-direct epilogue: full-sector stores, no smem staging.
    // fragment: rows r, r+8 (r = wm*32+mi*16+g), cols c, c+1 (c = wn*64+ni*8+2tq)
    int g = lane >> 2, tq = lane & 3;
    int r0 = bi * 128, c0 = bj * 128;
    bool interior = (bi < NT - 1) && (bj < NT - 1);

    if (interior) {
#pragma unroll
        for (int mi = 0; mi < 2; mi++)
#pragma unroll
            for (int ni = 0; ni < 8; ni++) {
                float* d = acc[mi][ni];
                int r = r0 + wm * 32 + mi * 16 + g;
                int c = c0 + wn * 64 + ni * 8 + 2 * tq;
                // direct: float2, 4 tq-lanes = 32B sector
                *(float2*)&out[(size_t)r * N_NODES + c]       = make_float2(d[0], d[1]);
                *(float2*)&out[(size_t)(r + 8) * N_NODES + c] = make_float2(d[2], d[3]);
                if (!diag) {
                    // mirror: scalar; per STG, 4 rows x 8 consecutive cols = 4 full sectors
                    out[(size_t)c * N_NODES + r]           = d[0];
                    out[(size_t)(c + 1) * N_NODES + r]     = d[1];
                    out[(size_t)c * N_NODES + r + 8]       = d[2];
                    out[(size_t)(c + 1) * N_NODES + r + 8] = d[3];
                }
            }
    } else {
#pragma unroll
        for (int mi = 0; mi < 2; mi++)
#pragma unroll
            for (int ni = 0; ni < 8; ni++) {
                float* d = acc[mi][ni];
                int r = r0 + wm * 32 + mi * 16 + g;
                int c = c0 + wn * 64 + ni * 8 + 2 * tq;
#pragma unroll
                for (int q = 0; q < 4; q++) {
                    int rr = r + (q >> 1) * 8, cc = c + (q & 1);
                    if (rr < N_NODES && cc < N_NODES)
                        out[(size_t)rr * N_NODES + cc] = d[q];
                    if (!diag && rr < N_NODES && cc < N_NODES)
                        out[(size_t)cc * N_NODES + rr] = d[q];
                }
            }
    }
}

extern "C" void kernel_launch(void* const* d_in, const int* in_sizes, int n_in,
                              void* d_out, int out_size) {
    const float* x  = nullptr;
    const int*   ei = nullptr;
    const float* W  = nullptr;
    const float* b  = nullptr;
    for (int i = 0; i < n_in; i++) {
        switch (in_sizes[i]) {
            case N_NODES * NHID: x  = (const float*)d_in[i]; break;
            case 2 * NEDGE:      ei = (const int*)d_in[i];   break;
            case NHID * NHID:    W  = (const float*)d_in[i]; break;
            case NHID:           b  = (const float*)d_in[i]; break;
            default: break;
        }
    }
    float* out = (float*)d_out;

    static int smem_set = 0;
    if (!smem_set) {
        cudaFuncSetAttribute(k_gemm, cudaFuncAttributeMaxDynamicSharedMemorySize,
                             GEMM_SMEM);
        smem_set = 1;
    }

    k_zero <<<(N_NODES + 255) / 256, 256>>>();
    k_hist <<<(NEDGE + 255) / 256, 256>>>(ei);
    k_scan <<<1, 256>>>();
    k_fill <<<(NEDGE + 255) / 256, 256>>>(ei);
    k_xw   <<<N_NODES, NHID>>>(x, W);
    k_spmm <<<N_NODES, NHID>>>(b);
    k_gemm <<<NB, 256, GEMM_SMEM>>>(out);
}